// round 2
// baseline (speedup 1.0000x reference)
#include <cuda_runtime.h>
#include <cuda_bf16.h>
#include <math_constants.h>

// Problem constants (fixed: B=4, N=M=8192, C=3, k=16)
#define BB 4
#define NN 8192
#define MM 8192
#define KK 16
#define SPLIT 4
#define CHUNK (MM / SPLIT)          // 2048
#define BLOCK 128
#define NQ (BB * NN)                // 32768 queries
#define NT (NQ * SPLIT)             // 131072 chunk-threads
#define CAP 448                     // survivor buffer depth per thread
#define SAMPLE_M 128                // sample size for threshold
#define SAMPLE_R 8                  // threshold = 8th smallest of sample

// Static scratch (allowed: __device__ globals, allocated at module load)
__device__ float4         g_p2[BB * MM];          // packed candidates (x,y,z,|p|^2)
__device__ unsigned short g_buf[CAP * NT];        // survivor indices, [slot][thread]
__device__ float          g_pd[NT * KK];          // per-chunk partial dists (sqrt'd, sorted)
__device__ int            g_pi[NT * KK];          // per-chunk partial ids

// ---------------------------------------------------------------------------
// Prep: pack xyz2 -> float4 with norm (reference rounding: (x*x+y*y)+z*z)
// ---------------------------------------------------------------------------
__global__ void knn_prep(const float* __restrict__ xyz2) {
    int t = blockIdx.x * blockDim.x + threadIdx.x;
    if (t < BB * MM) {
        float x = xyz2[3 * t + 0];
        float y = xyz2[3 * t + 1];
        float z = xyz2[3 * t + 2];
        float n = __fadd_rn(__fadd_rn(__fmul_rn(x, x), __fmul_rn(y, y)),
                            __fmul_rn(z, z));
        g_p2[t] = make_float4(x, y, z, n);
    }
}

// d2 arithmetic — identical to the validated round-1 kernel.
__device__ __forceinline__ float dist2(float4 p, float x, float y, float z, float n1) {
    float dot = __fmaf_rn(z, p.z, __fmaf_rn(y, p.y, __fmul_rn(x, p.x)));
    return __fadd_rn(__fadd_rn(__fmul_rn(-2.0f, dot), n1), p.w);
}

// Exact sorted (d2, ci) insert; increasing-ci arrival + strict < => lower-index tie rule.
#define INSERT16(d2v, civ)                                              \
    do {                                                                \
        _Pragma("unroll")                                               \
        for (int jj = KK - 1; jj > 0; --jj) {                           \
            bool sh = (d2v) < dk[jj - 1];                               \
            bool he = (!sh) && ((d2v) < dk[jj]);                        \
            float nd = sh ? dk[jj - 1] : (he ? (d2v) : dk[jj]);         \
            int   ni = sh ? idv[jj - 1] : (he ? (civ) : idv[jj]);       \
            dk[jj] = nd; idv[jj] = ni;                                  \
        }                                                               \
        if ((d2v) < dk[0]) { dk[0] = (d2v); idv[0] = (civ); }           \
    } while (0)

// ---------------------------------------------------------------------------
// Main: per (query, chunk) thread. Sample -> threshold -> branchless filter ->
// exact refine over survivors (or exact full rescan fallback).
// ---------------------------------------------------------------------------
__global__ void __launch_bounds__(BLOCK) knn_filter(const float* __restrict__ xyz1) {
    __shared__ float4 sm[CHUNK];                      // 32 KB

    const int gtid = blockIdx.x * BLOCK + threadIdx.x;     // unique chunk-thread
    const int s = blockIdx.x & (SPLIT - 1);                // chunk id
    const int q = (blockIdx.x >> 2) * BLOCK + threadIdx.x; // query id
    const int b = q >> 13;                                 // batch (q / NN)
    const int cbase = s * CHUNK;

    // Load whole chunk tile into shared memory.
    const float4* __restrict__ src = g_p2 + b * MM + cbase;
    for (int i = threadIdx.x; i < CHUNK; i += BLOCK)
        sm[i] = src[i];
    __syncthreads();

    // Query point + norm (reference rounding)
    const float x = xyz1[3 * q + 0];
    const float y = xyz1[3 * q + 1];
    const float z = xyz1[3 * q + 2];
    const float n1 = __fadd_rn(__fadd_rn(__fmul_rn(x, x), __fmul_rn(y, y)),
                               __fmul_rn(z, z));

    // --- Stage 1: threshold from sample (smallest-8 of first 128, FMNMX chain)
    float sl[SAMPLE_R];
#pragma unroll
    for (int i = 0; i < SAMPLE_R; ++i) sl[i] = CUDART_INF_F;
#pragma unroll 4
    for (int j = 0; j < SAMPLE_M; ++j) {
        float d2 = dist2(sm[j], x, y, z, n1);
        if (d2 < sl[SAMPLE_R - 1]) {
#pragma unroll
            for (int jj = SAMPLE_R - 1; jj > 0; --jj)
                sl[jj] = fminf(fmaxf(d2, sl[jj - 1]), sl[jj]);
            sl[0] = fminf(sl[0], d2);
        }
    }
    const float T = sl[SAMPLE_R - 1];

    // --- Stage 2: branchless filter of all CHUNK candidates
    unsigned addr = (unsigned)gtid;
    const unsigned amax = (unsigned)(CAP - 1) * (unsigned)NT + (unsigned)gtid;
    int cnt = 0;
#pragma unroll 8
    for (int j = 0; j < CHUNK; ++j) {
        float d2 = dist2(sm[j], x, y, z, n1);
        bool keep = d2 <= T;
        g_buf[addr] = (unsigned short)j;      // unconditional; garbage slots ignored
        cnt += keep;
        addr = min(addr + (keep ? (unsigned)NT : 0u), amax);
    }

    // --- Stage 3: exact top-16 (d2, idx)
    float dk[KK];
    int   idv[KK];
#pragma unroll
    for (int i = 0; i < KK; ++i) { dk[i] = CUDART_INF_F; idv[i] = 0; }

    if (cnt >= KK && cnt <= CAP) {
        // refine over survivors only (scanned in increasing candidate order)
        unsigned a = (unsigned)gtid;
        for (int c = 0; c < cnt; ++c) {
            int j = g_buf[a];
            a += (unsigned)NT;
            float d2 = dist2(sm[j], x, y, z, n1);
            if (d2 < dk[KK - 1]) {
                int ci = cbase + j;
                INSERT16(d2, ci);
            }
        }
    } else {
        // exact fallback: full rescan of the chunk (rare: threshold mis-sized)
        for (int j = 0; j < CHUNK; ++j) {
            float d2 = dist2(sm[j], x, y, z, n1);
            if (d2 < dk[KK - 1]) {
                int ci = cbase + j;
                INSERT16(d2, ci);
            }
        }
    }

    // --- Stage 4: sqrt, stable (dist, idx) sort, write partial results
    float dist[KK];
#pragma unroll
    for (int i = 0; i < KK; ++i) dist[i] = __fsqrt_rn(dk[i]);

#pragma unroll
    for (int ph = 0; ph < KK; ++ph) {
#pragma unroll
        for (int i = 0; i < KK - 1; ++i) {
            if ((i & 1) == (ph & 1)) {
                bool sw = (dist[i] > dist[i + 1]) ||
                          (dist[i] == dist[i + 1] && idv[i] > idv[i + 1]);
                float td = sw ? dist[i + 1] : dist[i];
                float tD = sw ? dist[i]     : dist[i + 1];
                int   ti = sw ? idv[i + 1]  : idv[i];
                int   tI = sw ? idv[i]      : idv[i + 1];
                dist[i] = td; dist[i + 1] = tD;
                idv[i]  = ti; idv[i + 1]  = tI;
            }
        }
    }

    const int r = (q * SPLIT + s) * KK;
#pragma unroll
    for (int i = 0; i < KK; ++i) {
        g_pd[r + i] = dist[i];
        g_pi[r + i] = idv[i];
    }
}

// ---------------------------------------------------------------------------
// Merge: per query, 4-way merge of sorted (dist, idx) partial lists -> top-16.
// ---------------------------------------------------------------------------
__global__ void knn_merge(float* __restrict__ out, int write_both) {
    int q = blockIdx.x * blockDim.x + threadIdx.x;
    if (q >= NQ) return;

    const int r0 = (q * SPLIT + 0) * KK;
    const int r1 = (q * SPLIT + 1) * KK;
    const int r2 = (q * SPLIT + 2) * KK;
    const int r3 = (q * SPLIT + 3) * KK;

    int h0 = 0, h1 = 0, h2 = 0, h3 = 0;
    float d0 = g_pd[r0], d1 = g_pd[r1], d2 = g_pd[r2], d3 = g_pd[r3];
    int   i0 = g_pi[r0], i1 = g_pi[r1], i2 = g_pi[r2], i3 = g_pi[r3];

    const long base = (long)q * KK;
    const long off = (long)NQ * KK;

#pragma unroll
    for (int k = 0; k < KK; ++k) {
        bool l01 = (d0 < d1) || (d0 == d1 && i0 < i1);
        float dA = l01 ? d0 : d1; int iA = l01 ? i0 : i1;
        bool l23 = (d2 < d3) || (d2 == d3 && i2 < i3);
        float dB = l23 ? d2 : d3; int iB = l23 ? i2 : i3;
        bool lAB = (dA < dB) || (dA == dB && iA < iB);
        float dw = lAB ? dA : dB; int iw = lAB ? iA : iB;

        out[base + k] = dw;
        if (write_both) out[off + base + k] = (float)iw;

        int pick = lAB ? (l01 ? 0 : 1) : (l23 ? 2 : 3);
        if (pick == 0) {
            ++h0; bool v = h0 < KK;
            d0 = v ? g_pd[r0 + h0] : CUDART_INF_F;
            i0 = v ? g_pi[r0 + h0] : 0x7fffffff;
        } else if (pick == 1) {
            ++h1; bool v = h1 < KK;
            d1 = v ? g_pd[r1 + h1] : CUDART_INF_F;
            i1 = v ? g_pi[r1 + h1] : 0x7fffffff;
        } else if (pick == 2) {
            ++h2; bool v = h2 < KK;
            d2 = v ? g_pd[r2 + h2] : CUDART_INF_F;
            i2 = v ? g_pi[r2 + h2] : 0x7fffffff;
        } else {
            ++h3; bool v = h3 < KK;
            d3 = v ? g_pd[r3 + h3] : CUDART_INF_F;
            i3 = v ? g_pi[r3 + h3] : 0x7fffffff;
        }
    }
}

extern "C" void kernel_launch(void* const* d_in, const int* in_sizes, int n_in,
                              void* d_out, int out_size) {
    const float* xyz1 = (const float*)d_in[0];
    const float* xyz2 = (const float*)d_in[1];
    float* out = (float*)d_out;

    int write_both = (out_size >= 2 * NQ * KK) ? 1 : 0;

    knn_prep<<<(BB * MM + 255) / 256, 256>>>(xyz2);
    knn_filter<<<NT / BLOCK, BLOCK>>>(xyz1);
    knn_merge<<<(NQ + 255) / 256, 256>>>(out, write_both);
}

// round 4
// speedup vs baseline: 1.6558x; 1.6558x over previous
#include <cuda_runtime.h>
#include <cuda_bf16.h>
#include <math_constants.h>

// Problem constants (fixed: B=4, N=M=8192, C=3, k=16)
#define BB 4
#define NN 8192
#define MM 8192
#define KK 16
#define SPLIT 4
#define CHUNK (MM / SPLIT)          // 2048 candidates per thread
#define SUB 512                     // sub-tile resident in smem
#define NSUB (CHUNK / SUB)          // 4
#define BLOCK 128
#define NQ (BB * NN)                // 32768 queries
#define NT (NQ * SPLIT)             // 131072 chunk-threads
#define CAP 48                      // survivor slots per thread per sub-tile
#define SAMPLE_M 128
#define SAMPLE_R 6                  // threshold = 6th smallest of sample

// Static scratch
__device__ float4 g_p2[BB * MM];    // packed candidates (x,y,z,|p|^2)
__device__ float  g_pd[NT * KK];    // per-chunk partial dists (sqrt'd, sorted)
__device__ int    g_pi[NT * KK];    // per-chunk partial ids

// ---------------------------------------------------------------------------
// Prep: pack xyz2 -> float4 with norm (reference rounding: (x*x+y*y)+z*z)
// ---------------------------------------------------------------------------
__global__ void knn_prep(const float* __restrict__ xyz2) {
    int t = blockIdx.x * blockDim.x + threadIdx.x;
    if (t < BB * MM) {
        float x = xyz2[3 * t + 0];
        float y = xyz2[3 * t + 1];
        float z = xyz2[3 * t + 2];
        float n = __fadd_rn(__fadd_rn(__fmul_rn(x, x), __fmul_rn(y, y)),
                            __fmul_rn(z, z));
        g_p2[t] = make_float4(x, y, z, n);
    }
}

// d2 arithmetic — identical to the validated round-1 kernel.
__device__ __forceinline__ float dist2(float4 p, float x, float y, float z, float n1) {
    float dot = __fmaf_rn(z, p.z, __fmaf_rn(y, p.y, __fmul_rn(x, p.x)));
    return __fadd_rn(__fadd_rn(__fmul_rn(-2.0f, dot), n1), p.w);
}

// Exact sorted (d2, ci) insert; increasing-ci arrival + strict < => lower-index tie rule.
#define INSERT16(d2v, civ)                                              \
    do {                                                                \
        _Pragma("unroll")                                               \
        for (int jj = KK - 1; jj > 0; --jj) {                           \
            bool sh = (d2v) < dk[jj - 1];                               \
            bool he = (!sh) && ((d2v) < dk[jj]);                        \
            float nd = sh ? dk[jj - 1] : (he ? (d2v) : dk[jj]);         \
            int   ni = sh ? idv[jj - 1] : (he ? (civ) : idv[jj]);       \
            dk[jj] = nd; idv[jj] = ni;                                  \
        }                                                               \
        if ((d2v) < dk[0]) { dk[0] = (d2v); idv[0] = (civ); }           \
    } while (0)

// ---------------------------------------------------------------------------
// Main: per (query, chunk) thread. Sample threshold -> branchless SMEM filter
// -> exact refine over survivors (rare exact-fallback full rescan).
// ---------------------------------------------------------------------------
__global__ void __launch_bounds__(BLOCK, 6) knn_filter(const float* __restrict__ xyz1) {
    __shared__ float4 tile[SUB];                 // 8 KB
    __shared__ int    buf[(CAP + 1) * BLOCK];    // 24.5 KB, [slot][tid], conflict-free

    const int tid = threadIdx.x;
    const int s = blockIdx.x & (SPLIT - 1);                 // chunk id
    const int q = (blockIdx.x >> 2) * BLOCK + tid;          // query id
    const int b = q >> 13;                                  // batch
    const int cbase = s * CHUNK;
    const float4* __restrict__ src = g_p2 + b * MM + cbase;

    // Query point + norm (reference rounding)
    const float x = xyz1[3 * q + 0];
    const float y = xyz1[3 * q + 1];
    const float z = xyz1[3 * q + 2];
    const float n1 = __fadd_rn(__fadd_rn(__fmul_rn(x, x), __fmul_rn(y, y)),
                               __fmul_rn(z, z));

    float dk[KK];
    int   idv[KK];
#pragma unroll
    for (int i = 0; i < KK; ++i) { dk[i] = CUDART_INF_F; idv[i] = 0; }

    float T = CUDART_INF_F;
    int tot = 0;
    bool bad = false;

    for (int st = 0; st < NSUB; ++st) {
        __syncthreads();                          // protect tile+buf from prior refine
#pragma unroll
        for (int i = tid; i < SUB; i += BLOCK)
            tile[i] = src[st * SUB + i];
        __syncthreads();

        if (st == 0) {
            // Threshold: branchless smallest-SAMPLE_R chain over first 128 cands.
            float sl[SAMPLE_R];
#pragma unroll
            for (int i = 0; i < SAMPLE_R; ++i) sl[i] = CUDART_INF_F;
#pragma unroll 4
            for (int j = 0; j < SAMPLE_M; ++j) {
                float d2 = dist2(tile[j], x, y, z, n1);
#pragma unroll
                for (int jj = SAMPLE_R - 1; jj > 0; --jj)
                    sl[jj] = fminf(fmaxf(d2, sl[jj - 1]), sl[jj]);
                sl[0] = fminf(sl[0], d2);
            }
            T = sl[SAMPLE_R - 1];
        }

        // Branchless filter: unconditional STS of index, predicated slot advance.
        int off = 0;
#pragma unroll 8
        for (int j = 0; j < SUB; ++j) {
            float4 p = tile[j];
            float d2 = dist2(p, x, y, z, n1);
            bool keep = d2 <= T;
            buf[off + tid] = j;                   // row CAP is a sacrificial slot
            off = min(off + (keep ? BLOCK : 0), CAP * BLOCK);
        }
        int cnt = off >> 7;                       // BLOCK == 128

        if (cnt >= CAP) {
            bad = true;                           // overflow: slots were lost
        } else {
            tot += cnt;
            for (int c = 0; c < cnt; ++c) {
                int j = buf[c * BLOCK + tid];
                float d2 = dist2(tile[j], x, y, z, n1);
                if (d2 < dk[KK - 1]) {
                    int ci = cbase + st * SUB + j;
                    INSERT16(d2, ci);
                }
            }
        }
    }

    if (bad || tot < KK) {
        // Exact fallback: full rescan of the chunk from L2-resident global.
#pragma unroll
        for (int i = 0; i < KK; ++i) { dk[i] = CUDART_INF_F; idv[i] = 0; }
        for (int j = 0; j < CHUNK; ++j) {
            float4 p = src[j];
            float d2 = dist2(p, x, y, z, n1);
            if (d2 < dk[KK - 1]) {
                int ci = cbase + j;
                INSERT16(d2, ci);
            }
        }
    }

    // sqrt, stable (dist, idx) sort, write partial results
    float dist[KK];
#pragma unroll
    for (int i = 0; i < KK; ++i) dist[i] = __fsqrt_rn(dk[i]);

#pragma unroll
    for (int ph = 0; ph < KK; ++ph) {
#pragma unroll
        for (int i = 0; i < KK - 1; ++i) {
            if ((i & 1) == (ph & 1)) {
                bool sw = (dist[i] > dist[i + 1]) ||
                          (dist[i] == dist[i + 1] && idv[i] > idv[i + 1]);
                float td = sw ? dist[i + 1] : dist[i];
                float tD = sw ? dist[i]     : dist[i + 1];
                int   ti = sw ? idv[i + 1]  : idv[i];
                int   tI = sw ? idv[i]      : idv[i + 1];
                dist[i] = td; dist[i + 1] = tD;
                idv[i]  = ti; idv[i + 1]  = tI;
            }
        }
    }

    const int r = (q * SPLIT + s) * KK;
#pragma unroll
    for (int i = 0; i < KK; ++i) {
        g_pd[r + i] = dist[i];
        g_pi[r + i] = idv[i];
    }
}

// ---------------------------------------------------------------------------
// Merge: per query, 4-way merge of sorted (dist, idx) partial lists -> top-16.
// (unchanged from the round-2 kernel; numerics validated)
// ---------------------------------------------------------------------------
__global__ void knn_merge(float* __restrict__ out, int write_both) {
    int q = blockIdx.x * blockDim.x + threadIdx.x;
    if (q >= NQ) return;

    const int r0 = (q * SPLIT + 0) * KK;
    const int r1 = (q * SPLIT + 1) * KK;
    const int r2 = (q * SPLIT + 2) * KK;
    const int r3 = (q * SPLIT + 3) * KK;

    int h0 = 0, h1 = 0, h2 = 0, h3 = 0;
    float d0 = g_pd[r0], d1 = g_pd[r1], d2 = g_pd[r2], d3 = g_pd[r3];
    int   i0 = g_pi[r0], i1 = g_pi[r1], i2 = g_pi[r2], i3 = g_pi[r3];

    const long base = (long)q * KK;
    const long off = (long)NQ * KK;

#pragma unroll
    for (int k = 0; k < KK; ++k) {
        bool l01 = (d0 < d1) || (d0 == d1 && i0 < i1);
        float dA = l01 ? d0 : d1; int iA = l01 ? i0 : i1;
        bool l23 = (d2 < d3) || (d2 == d3 && i2 < i3);
        float dB = l23 ? d2 : d3; int iB = l23 ? i2 : i3;
        bool lAB = (dA < dB) || (dA == dB && iA < iB);
        float dw = lAB ? dA : dB; int iw = lAB ? iA : iB;

        out[base + k] = dw;
        if (write_both) out[off + base + k] = (float)iw;

        int pick = lAB ? (l01 ? 0 : 1) : (l23 ? 2 : 3);
        if (pick == 0) {
            ++h0; bool v = h0 < KK;
            d0 = v ? g_pd[r0 + h0] : CUDART_INF_F;
            i0 = v ? g_pi[r0 + h0] : 0x7fffffff;
        } else if (pick == 1) {
            ++h1; bool v = h1 < KK;
            d1 = v ? g_pd[r1 + h1] : CUDART_INF_F;
            i1 = v ? g_pi[r1 + h1] : 0x7fffffff;
        } else if (pick == 2) {
            ++h2; bool v = h2 < KK;
            d2 = v ? g_pd[r2 + h2] : CUDART_INF_F;
            i2 = v ? g_pi[r2 + h2] : 0x7fffffff;
        } else {
            ++h3; bool v = h3 < KK;
            d3 = v ? g_pd[r3 + h3] : CUDART_INF_F;
            i3 = v ? g_pi[r3 + h3] : 0x7fffffff;
        }
    }
}

extern "C" void kernel_launch(void* const* d_in, const int* in_sizes, int n_in,
                              void* d_out, int out_size) {
    const float* xyz1 = (const float*)d_in[0];
    const float* xyz2 = (const float*)d_in[1];
    float* out = (float*)d_out;

    int write_both = (out_size >= 2 * NQ * KK) ? 1 : 0;

    knn_prep<<<(BB * MM + 255) / 256, 256>>>(xyz2);
    knn_filter<<<NT / BLOCK, BLOCK>>>(xyz1);
    knn_merge<<<(NQ + 255) / 256, 256>>>(out, write_both);
}

// round 5
// speedup vs baseline: 3.7478x; 2.2634x over previous
#include <cuda_runtime.h>
#include <cuda_bf16.h>
#include <math_constants.h>

// Problem constants (fixed: B=4, N=M=8192, C=3, k=16)
#define BB 4
#define NN 8192
#define MM 8192
#define KK 16
#define SPLIT 4
#define CHUNK (MM / SPLIT)          // 2048 candidates per thread
#define SUB 512                     // sub-tile resident in smem
#define NSUB (CHUNK / SUB)          // 4
#define BLOCK 128
#define NQ (BB * NN)                // 32768 queries
#define NT (NQ * SPLIT)             // 131072 chunk-threads
#define CAP 63                      // survivor slots per thread per sub-tile
#define SAMPLE_M 128
#define SAMPLE_R 6                  // threshold = 6th smallest of sample

// Static scratch
__device__ float4 g_p2[BB * MM];    // packed candidates (x,y,z,|p|^2)
__device__ float  g_pd[NT * KK];    // per-chunk partial dists (sqrt'd, sorted)
__device__ int    g_pi[NT * KK];    // per-chunk partial ids

// ---------------------------------------------------------------------------
// Prep: pack xyz2 -> float4 with norm (reference rounding: (x*x+y*y)+z*z)
// ---------------------------------------------------------------------------
__global__ void knn_prep(const float* __restrict__ xyz2) {
    int t = blockIdx.x * blockDim.x + threadIdx.x;
    if (t < BB * MM) {
        float x = xyz2[3 * t + 0];
        float y = xyz2[3 * t + 1];
        float z = xyz2[3 * t + 2];
        float n = __fadd_rn(__fadd_rn(__fmul_rn(x, x), __fmul_rn(y, y)),
                            __fmul_rn(z, z));
        g_p2[t] = make_float4(x, y, z, n);
    }
}

// d2 arithmetic — identical to the validated round-1 kernel.
__device__ __forceinline__ float dist2(float4 p, float x, float y, float z, float n1) {
    float dot = __fmaf_rn(z, p.z, __fmaf_rn(y, p.y, __fmul_rn(x, p.x)));
    return __fadd_rn(__fadd_rn(__fmul_rn(-2.0f, dot), n1), p.w);
}

// Exact sorted (d2, ci) insert; increasing-ci arrival + strict < => lower-index tie rule.
#define INSERT16(d2v, civ)                                              \
    do {                                                                \
        _Pragma("unroll")                                               \
        for (int jj = KK - 1; jj > 0; --jj) {                           \
            bool sh = (d2v) < dk[jj - 1];                               \
            bool he = (!sh) && ((d2v) < dk[jj]);                        \
            float nd = sh ? dk[jj - 1] : (he ? (d2v) : dk[jj]);         \
            int   ni = sh ? idv[jj - 1] : (he ? (civ) : idv[jj]);       \
            dk[jj] = nd; idv[jj] = ni;                                  \
        }                                                               \
        if ((d2v) < dk[0]) { dk[0] = (d2v); idv[0] = (civ); }           \
    } while (0)

// ---------------------------------------------------------------------------
// Main: per (query, chunk) thread. Sample threshold -> branchless SMEM filter
// -> exact refine over survivors. Overflowing sub-tiles are recovered EXACTLY
// and LOCALLY (dense rescan of the smem-resident sub-tile). Global fallback
// only for the ultra-rare tot<16 underflow.
// ---------------------------------------------------------------------------
__global__ void __launch_bounds__(BLOCK, 7) knn_filter(const float* __restrict__ xyz1) {
    __shared__ float4         tile[SUB];                 // 8 KB
    __shared__ unsigned short buf[(CAP + 1) * BLOCK];    // 16.4 KB, [slot][tid]

    const int tid = threadIdx.x;
    const int s = blockIdx.x & (SPLIT - 1);                 // chunk id
    const int q = (blockIdx.x >> 2) * BLOCK + tid;          // query id
    const int b = q >> 13;                                  // batch
    const int cbase = s * CHUNK;
    const float4* __restrict__ src = g_p2 + b * MM + cbase;

    // Query point + norm (reference rounding)
    const float x = xyz1[3 * q + 0];
    const float y = xyz1[3 * q + 1];
    const float z = xyz1[3 * q + 2];
    const float n1 = __fadd_rn(__fadd_rn(__fmul_rn(x, x), __fmul_rn(y, y)),
                               __fmul_rn(z, z));

    float dk[KK];
    int   idv[KK];
#pragma unroll
    for (int i = 0; i < KK; ++i) { dk[i] = CUDART_INF_F; idv[i] = 0; }

    float T = CUDART_INF_F;
    int tot = 0;

    for (int st = 0; st < NSUB; ++st) {
        __syncthreads();                          // protect tile+buf from prior refine
#pragma unroll
        for (int i = tid; i < SUB; i += BLOCK)
            tile[i] = src[st * SUB + i];
        __syncthreads();

        if (st == 0) {
            // Threshold: branchless smallest-SAMPLE_R chain over first 128 cands.
            float sl[SAMPLE_R];
#pragma unroll
            for (int i = 0; i < SAMPLE_R; ++i) sl[i] = CUDART_INF_F;
#pragma unroll 4
            for (int j = 0; j < SAMPLE_M; ++j) {
                float d2 = dist2(tile[j], x, y, z, n1);
#pragma unroll
                for (int jj = SAMPLE_R - 1; jj > 0; --jj)
                    sl[jj] = fminf(fmaxf(d2, sl[jj - 1]), sl[jj]);
                sl[0] = fminf(sl[0], d2);
            }
            T = sl[SAMPLE_R - 1];
        }

        // Branchless filter: unconditional STS of index, predicated slot advance.
        int off = 0;
#pragma unroll 8
        for (int j = 0; j < SUB; ++j) {
            float d2 = dist2(tile[j], x, y, z, n1);
            bool keep = d2 <= T;
            buf[off + tid] = (unsigned short)j;   // row CAP is a sacrificial slot
            off = min(off + (keep ? BLOCK : 0), CAP * BLOCK);
        }
        const int  cnt = off >> 7;                // BLOCK == 128
        const bool ov  = (cnt == CAP);            // may have lost entries

        // Refine. Normal lanes walk their survivor list; overflow lanes walk
        // the ENTIRE sub-tile (exact, local recovery). Unified loop so only
        // one INSERT16 instantiation lives here.
        const int lim = ov ? SUB : cnt;
        tot += cnt;                               // ov => cnt==CAP >= 16, still certifies
        const int sbase = cbase + st * SUB;
        for (int c = 0; c < lim; ++c) {
            int jb = buf[min(c, CAP) * BLOCK + tid];   // in-bounds for all c
            int j  = ov ? c : jb;
            float d2 = dist2(tile[j], x, y, z, n1);
            if (d2 < dk[KK - 1]) {
                int ci = sbase + j;
                INSERT16(d2, ci);
            }
        }
    }

    if (tot < KK) {
        // Exact global fallback (threshold too tight): full rescan of chunk.
#pragma unroll
        for (int i = 0; i < KK; ++i) { dk[i] = CUDART_INF_F; idv[i] = 0; }
        for (int j = 0; j < CHUNK; ++j) {
            float4 p = src[j];
            float d2 = dist2(p, x, y, z, n1);
            if (d2 < dk[KK - 1]) {
                int ci = cbase + j;
                INSERT16(d2, ci);
            }
        }
    }

    // sqrt, stable (dist, idx) sort, write partial results
    float dist[KK];
#pragma unroll
    for (int i = 0; i < KK; ++i) dist[i] = __fsqrt_rn(dk[i]);

#pragma unroll
    for (int ph = 0; ph < KK; ++ph) {
#pragma unroll
        for (int i = 0; i < KK - 1; ++i) {
            if ((i & 1) == (ph & 1)) {
                bool sw = (dist[i] > dist[i + 1]) ||
                          (dist[i] == dist[i + 1] && idv[i] > idv[i + 1]);
                float td = sw ? dist[i + 1] : dist[i];
                float tD = sw ? dist[i]     : dist[i + 1];
                int   ti = sw ? idv[i + 1]  : idv[i];
                int   tI = sw ? idv[i]      : idv[i + 1];
                dist[i] = td; dist[i + 1] = tD;
                idv[i]  = ti; idv[i + 1]  = tI;
            }
        }
    }

    const int r = (q * SPLIT + s) * KK;
#pragma unroll
    for (int i = 0; i < KK; ++i) {
        g_pd[r + i] = dist[i];
        g_pi[r + i] = idv[i];
    }
}

// ---------------------------------------------------------------------------
// Merge: per query, 4-way merge of sorted (dist, idx) partial lists -> top-16.
// (numerics validated in earlier rounds; unchanged)
// ---------------------------------------------------------------------------
__global__ void knn_merge(float* __restrict__ out, int write_both) {
    int q = blockIdx.x * blockDim.x + threadIdx.x;
    if (q >= NQ) return;

    const int r0 = (q * SPLIT + 0) * KK;
    const int r1 = (q * SPLIT + 1) * KK;
    const int r2 = (q * SPLIT + 2) * KK;
    const int r3 = (q * SPLIT + 3) * KK;

    int h0 = 0, h1 = 0, h2 = 0, h3 = 0;
    float d0 = g_pd[r0], d1 = g_pd[r1], d2 = g_pd[r2], d3 = g_pd[r3];
    int   i0 = g_pi[r0], i1 = g_pi[r1], i2 = g_pi[r2], i3 = g_pi[r3];

    const long base = (long)q * KK;
    const long off = (long)NQ * KK;

#pragma unroll
    for (int k = 0; k < KK; ++k) {
        bool l01 = (d0 < d1) || (d0 == d1 && i0 < i1);
        float dA = l01 ? d0 : d1; int iA = l01 ? i0 : i1;
        bool l23 = (d2 < d3) || (d2 == d3 && i2 < i3);
        float dB = l23 ? d2 : d3; int iB = l23 ? i2 : i3;
        bool lAB = (dA < dB) || (dA == dB && iA < iB);
        float dw = lAB ? dA : dB; int iw = lAB ? iA : iB;

        out[base + k] = dw;
        if (write_both) out[off + base + k] = (float)iw;

        int pick = lAB ? (l01 ? 0 : 1) : (l23 ? 2 : 3);
        if (pick == 0) {
            ++h0; bool v = h0 < KK;
            d0 = v ? g_pd[r0 + h0] : CUDART_INF_F;
            i0 = v ? g_pi[r0 + h0] : 0x7fffffff;
        } else if (pick == 1) {
            ++h1; bool v = h1 < KK;
            d1 = v ? g_pd[r1 + h1] : CUDART_INF_F;
            i1 = v ? g_pi[r1 + h1] : 0x7fffffff;
        } else if (pick == 2) {
            ++h2; bool v = h2 < KK;
            d2 = v ? g_pd[r2 + h2] : CUDART_INF_F;
            i2 = v ? g_pi[r2 + h2] : 0x7fffffff;
        } else {
            ++h3; bool v = h3 < KK;
            d3 = v ? g_pd[r3 + h3] : CUDART_INF_F;
            i3 = v ? g_pi[r3 + h3] : 0x7fffffff;
        }
    }
}

extern "C" void kernel_launch(void* const* d_in, const int* in_sizes, int n_in,
                              void* d_out, int out_size) {
    const float* xyz1 = (const float*)d_in[0];
    const float* xyz2 = (const float*)d_in[1];
    float* out = (float*)d_out;

    int write_both = (out_size >= 2 * NQ * KK) ? 1 : 0;

    knn_prep<<<(BB * MM + 255) / 256, 256>>>(xyz2);
    knn_filter<<<NT / BLOCK, BLOCK>>>(xyz1);
    knn_merge<<<(NQ + 255) / 256, 256>>>(out, write_both);
}

// round 7
// speedup vs baseline: 4.1738x; 1.1137x over previous
#include <cuda_runtime.h>
#include <cuda_bf16.h>
#include <math_constants.h>

// Problem constants (fixed: B=4, N=M=8192, C=3, k=16)
#define BB 4
#define NN 8192
#define MM 8192
#define KK 16
#define SPLIT 4
#define CHUNK (MM / SPLIT)          // 2048 candidates per thread
#define SUB 256                     // sub-tile resident in smem
#define NSUB (CHUNK / SUB)          // 8
#define NW (SUB / 32)               // 8 mask words per sub-tile
#define BLOCK 128
#define NQ (BB * NN)                // 32768 queries
#define NT (NQ * SPLIT)             // 131072 chunk-threads
#define SAMPLE_M 128
#define SAMPLE_R 6                  // threshold = 6th-closest of sample
#define SLACK 1e-3f

// Static scratch
__device__ float4 g_p2[BB * MM];    // packed candidates (x,y,z, -0.5*|p|^2)
__device__ float  g_pd[NT * KK];    // per-chunk partial dists (sqrt'd, sorted)
__device__ int    g_pi[NT * KK];    // per-chunk partial ids

// ---------------------------------------------------------------------------
// Prep: pack xyz2 -> float4. Norm uses reference rounding ((x*x+y*y)+z*z);
// the stored w = -0.5*n is EXACT (power-of-two multiply), so refine recovers
// the bit-exact norm as -2*w.
// ---------------------------------------------------------------------------
__global__ void knn_prep(const float* __restrict__ xyz2) {
    int t = blockIdx.x * blockDim.x + threadIdx.x;
    if (t < BB * MM) {
        float x = xyz2[3 * t + 0];
        float y = xyz2[3 * t + 1];
        float z = xyz2[3 * t + 2];
        float n = __fadd_rn(__fadd_rn(__fmul_rn(x, x), __fmul_rn(y, y)),
                            __fmul_rn(z, z));
        g_p2[t] = make_float4(x, y, z, __fmul_rn(-0.5f, n));
    }
}

// Exact reference-rounded d2 (identical arithmetic to the validated kernels).
// p.w = -0.5*n2 exactly, so n2 = -2*p.w is bit-exact.
__device__ __forceinline__ float dist2x(float4 p, float x, float y, float z, float n1) {
    float dot = __fmaf_rn(z, p.z, __fmaf_rn(y, p.y, __fmul_rn(x, p.x)));
    float n2  = __fmul_rn(-2.0f, p.w);
    return __fadd_rn(__fadd_rn(__fmul_rn(-2.0f, dot), n1), n2);
}

// Filter metric: val = dot - n2/2 (3 FMAs). Larger val == closer candidate.
__device__ __forceinline__ float fval(float4 p, float x, float y, float z) {
    return __fmaf_rn(x, p.x, __fmaf_rn(y, p.y, __fmaf_rn(z, p.z, p.w)));
}

// Exact sorted (d2, ci) insert; increasing-ci arrival + strict < => lower-index tie rule.
#define INSERT16(d2v, civ)                                              \
    do {                                                                \
        _Pragma("unroll")                                               \
        for (int jj = KK - 1; jj > 0; --jj) {                           \
            bool sh = (d2v) < dk[jj - 1];                               \
            bool he = (!sh) && ((d2v) < dk[jj]);                        \
            float nd = sh ? dk[jj - 1] : (he ? (d2v) : dk[jj]);         \
            int   ni = sh ? idv[jj - 1] : (he ? (civ) : idv[jj]);       \
            dk[jj] = nd; idv[jj] = ni;                                  \
        }                                                               \
        if ((d2v) < dk[0]) { dk[0] = (d2v); idv[0] = (civ); }           \
    } while (0)

// ---------------------------------------------------------------------------
// Main: per (query, chunk) thread. Sample threshold -> pure-read bitmask
// filter (no in-loop stores) -> per-word ffs refine with exact d2.
// Certification: count survivors with exact d2 <= Tcert; >=16 proves top-16
// is contained in the survivor set. Underflow => exact full rescan.
// ---------------------------------------------------------------------------
__global__ void __launch_bounds__(BLOCK, 7) knn_filter(const float* __restrict__ xyz1) {
    __shared__ float4 tile[SUB];                  // 4 KB

    const int tid = threadIdx.x;
    const int s = blockIdx.x & (SPLIT - 1);                 // chunk id
    const int q = (blockIdx.x >> 2) * BLOCK + tid;          // query id
    const int b = q >> 13;                                  // batch
    const int cbase = s * CHUNK;
    const float4* __restrict__ src = g_p2 + b * MM + cbase;

    // Query point + norm (reference rounding)
    const float x = xyz1[3 * q + 0];
    const float y = xyz1[3 * q + 1];
    const float z = xyz1[3 * q + 2];
    const float n1 = __fadd_rn(__fadd_rn(__fmul_rn(x, x), __fmul_rn(y, y)),
                               __fmul_rn(z, z));

    float dk[KK];
    int   idv[KK];
#pragma unroll
    for (int i = 0; i < KK; ++i) { dk[i] = CUDART_INF_F; idv[i] = 0; }

    float hqd = 0.0f, Tcert = 0.0f;
    int c16 = 0;

    for (int st = 0; st < NSUB; ++st) {
        __syncthreads();                          // tile reused across sub-tiles
#pragma unroll
        for (int i = tid; i < SUB; i += BLOCK)
            tile[i] = src[st * SUB + i];
        __syncthreads();

        if (st == 0) {
            // Threshold: branchless LARGEST-6 val chain over first 128 cands.
            float sl[SAMPLE_R];
#pragma unroll
            for (int i = 0; i < SAMPLE_R; ++i) sl[i] = -CUDART_INF_F;
#pragma unroll 4
            for (int j = 0; j < SAMPLE_M; ++j) {
                float v = fval(tile[j], x, y, z);
#pragma unroll
                for (int jj = SAMPLE_R - 1; jj > 0; --jj)
                    sl[jj] = fmaxf(fminf(v, sl[jj - 1]), sl[jj]);
                sl[0] = fmaxf(sl[0], v);
            }
            float hq = sl[SAMPLE_R - 1];          // 6th-largest val
            hqd   = hq - SLACK;                   // conservative keep threshold
            // excluded => val < hqd => exact d2 > Tcert (SLACK >> fp error)
            Tcert = __fadd_rn(__fmaf_rn(-2.0f, hq, n1), SLACK);
        }

        const int sbase = cbase + st * SUB;
#pragma unroll
        for (int wi = 0; wi < NW; ++wi) {
            // --- pure-read mask pass: 32 independent LDS.128 + 3 FMA + setp/or
            unsigned m = 0;
#pragma unroll
            for (int bb = 0; bb < 32; ++bb) {
                float v = fval(tile[wi * 32 + bb], x, y, z);
                if (v >= hqd) m |= (1u << bb);
            }
            // --- drain survivors in ascending index order (tie rule)
            while (m) {
                int bb = __ffs(m) - 1;
                m &= m - 1;
                int j = wi * 32 + bb;
                float d2 = dist2x(tile[j], x, y, z, n1);
                c16 += (d2 <= Tcert);
                if (d2 < dk[KK - 1]) {
                    int ci = sbase + j;
                    INSERT16(d2, ci);
                }
            }
        }
    }

    if (c16 < KK) {
        // Exact fallback (threshold too tight — astronomically rare):
#pragma unroll
        for (int i = 0; i < KK; ++i) { dk[i] = CUDART_INF_F; idv[i] = 0; }
        for (int j = 0; j < CHUNK; ++j) {
            float4 p = src[j];
            float d2 = dist2x(p, x, y, z, n1);
            if (d2 < dk[KK - 1]) {
                int ci = cbase + j;
                INSERT16(d2, ci);
            }
        }
    }

    // sqrt, stable (dist, idx) sort, write partial results
    float dist[KK];
#pragma unroll
    for (int i = 0; i < KK; ++i) dist[i] = __fsqrt_rn(dk[i]);

#pragma unroll
    for (int ph = 0; ph < KK; ++ph) {
#pragma unroll
        for (int i = 0; i < KK - 1; ++i) {
            if ((i & 1) == (ph & 1)) {
                bool sw = (dist[i] > dist[i + 1]) ||
                          (dist[i] == dist[i + 1] && idv[i] > idv[i + 1]);
                float td = sw ? dist[i + 1] : dist[i];
                float tD = sw ? dist[i]     : dist[i + 1];
                int   ti = sw ? idv[i + 1]  : idv[i];
                int   tI = sw ? idv[i]      : idv[i + 1];
                dist[i] = td; dist[i + 1] = tD;
                idv[i]  = ti; idv[i + 1]  = tI;
            }
        }
    }

    const int r = (q * SPLIT + s) * KK;
#pragma unroll
    for (int i = 0; i < KK; ++i) {
        g_pd[r + i] = dist[i];
        g_pi[r + i] = idv[i];
    }
}

// ---------------------------------------------------------------------------
// Merge: per query, 4-way merge of sorted (dist, idx) partial lists -> top-16.
// (numerics validated in earlier rounds; unchanged)
// ---------------------------------------------------------------------------
__global__ void knn_merge(float* __restrict__ out, int write_both) {
    int q = blockIdx.x * blockDim.x + threadIdx.x;
    if (q >= NQ) return;

    const int r0 = (q * SPLIT + 0) * KK;
    const int r1 = (q * SPLIT + 1) * KK;
    const int r2 = (q * SPLIT + 2) * KK;
    const int r3 = (q * SPLIT + 3) * KK;

    int h0 = 0, h1 = 0, h2 = 0, h3 = 0;
    float d0 = g_pd[r0], d1 = g_pd[r1], d2 = g_pd[r2], d3 = g_pd[r3];
    int   i0 = g_pi[r0], i1 = g_pi[r1], i2 = g_pi[r2], i3 = g_pi[r3];

    const long base = (long)q * KK;
    const long off = (long)NQ * KK;

#pragma unroll
    for (int k = 0; k < KK; ++k) {
        bool l01 = (d0 < d1) || (d0 == d1 && i0 < i1);
        float dA = l01 ? d0 : d1; int iA = l01 ? i0 : i1;
        bool l23 = (d2 < d3) || (d2 == d3 && i2 < i3);
        float dB = l23 ? d2 : d3; int iB = l23 ? i2 : i3;
        bool lAB = (dA < dB) || (dA == dB && iA < iB);
        float dw = lAB ? dA : dB; int iw = lAB ? iA : iB;

        out[base + k] = dw;
        if (write_both) out[off + base + k] = (float)iw;

        int pick = lAB ? (l01 ? 0 : 1) : (l23 ? 2 : 3);
        if (pick == 0) {
            ++h0; bool v = h0 < KK;
            d0 = v ? g_pd[r0 + h0] : CUDART_INF_F;
            i0 = v ? g_pi[r0 + h0] : 0x7fffffff;
        } else if (pick == 1) {
            ++h1; bool v = h1 < KK;
            d1 = v ? g_pd[r1 + h1] : CUDART_INF_F;
            i1 = v ? g_pi[r1 + h1] : 0x7fffffff;
        } else if (pick == 2) {
            ++h2; bool v = h2 < KK;
            d2 = v ? g_pd[r2 + h2] : CUDART_INF_F;
            i2 = v ? g_pi[r2 + h2] : 0x7fffffff;
        } else {
            ++h3; bool v = h3 < KK;
            d3 = v ? g_pd[r3 + h3] : CUDART_INF_F;
            i3 = v ? g_pi[r3 + h3] : 0x7fffffff;
        }
    }
}

extern "C" void kernel_launch(void* const* d_in, const int* in_sizes, int n_in,
                              void* d_out, int out_size) {
    const float* xyz1 = (const float*)d_in[0];
    const float* xyz2 = (const float*)d_in[1];
    float* out = (float*)d_out;

    int write_both = (out_size >= 2 * NQ * KK) ? 1 : 0;

    knn_prep<<<(BB * MM + 255) / 256, 256>>>(xyz2);
    knn_filter<<<NT / BLOCK, BLOCK>>>(xyz1);
    knn_merge<<<(NQ + 255) / 256, 256>>>(out, write_both);
}